// round 2
// baseline (speedup 1.0000x reference)
#include <cuda_runtime.h>

// Batched 256-point complex DFT, out = FFT(x) / sqrt(256).
// Four-step algorithm, 256 = 16 x 16, fully shared-memory staged so every
// global access is a 128-bit coalesced vector op:
//   load float4 -> smem (linear) -> strided LDS -> fft16 -> tw2 twiddle ->
//   transposed STS -> row LDS -> fft16 -> linear STS -> float4 store.
// W16 twiddles are compile-time constants; the W256^{t*k} table (with the
// 1/16 scale folded in) is built once per block in [k][t] float2 layout so
// all reads are contiguous/broadcast (no bank conflicts).

#define NPT      256
#define FPB      16           // frames per block
#define BLOCK    256
#define ROWS     17           // padded row stride for the transpose (16+1)
#define FSTRIDE  272          // frame stride in shared; 272 % 32 == 16

__device__ __forceinline__ void dft4(
    float& r0, float& i0, float& r1, float& i1,
    float& r2, float& i2, float& r3, float& i3)
{
    float t0r = r0 + r2, t0i = i0 + i2;
    float t1r = r0 - r2, t1i = i0 - i2;
    float t2r = r1 + r3, t2i = i1 + i3;
    float t3r = r1 - r3, t3i = i1 - i3;
    r0 = t0r + t2r;  i0 = t0i + t2i;
    r2 = t0r - t2r;  i2 = t0i - t2i;
    r1 = t1r + t3i;  i1 = t1i - t3r;   // t1 - i*t3
    r3 = t1r - t3i;  i3 = t1i + t3r;   // t1 + i*t3
}

// In-register forward 16-pt DFT (two radix-4 stages, DIT).
// Output X[4*k1 + k2] lives in slot (4*k2 + k1); callers remap with rev4().
// W16 twiddles are immediates (no shared loads).
__device__ __forceinline__ void fft16(float* xr, float* xi)
{
    // W16^m = exp(-2*pi*i*m/16), m = 0..9 (only 1,2,3,4,6,9 used)
    constexpr float WR[10] = {
        1.f,  0.92387953251128674f,  0.70710678118654752f,  0.38268343236508977f,
        0.f, -0.38268343236508977f, -0.70710678118654752f, -0.92387953251128674f,
       -1.f, -0.92387953251128674f };
    constexpr float WI[10] = {
        0.f, -0.38268343236508977f, -0.70710678118654752f, -0.92387953251128674f,
       -1.f, -0.92387953251128674f, -0.70710678118654752f, -0.38268343236508977f,
        0.f,  0.38268343236508977f };

#pragma unroll
    for (int n1 = 0; n1 < 4; n1++) {
        dft4(xr[n1],    xi[n1],
             xr[n1+4],  xi[n1+4],
             xr[n1+8],  xi[n1+8],
             xr[n1+12], xi[n1+12]);
    }
#pragma unroll
    for (int n1 = 1; n1 < 4; n1++) {
#pragma unroll
        for (int k2 = 1; k2 < 4; k2++) {
            int s = n1 + 4 * k2;
            int m = n1 * k2;               // 1..9
            float wr = WR[m], wi = WI[m];
            float ar = xr[s], ai = xi[s];
            xr[s] = ar * wr - ai * wi;
            xi[s] = ar * wi + ai * wr;
        }
    }
#pragma unroll
    for (int k2 = 0; k2 < 4; k2++) {
        dft4(xr[4*k2+0], xi[4*k2+0],
             xr[4*k2+1], xi[4*k2+1],
             xr[4*k2+2], xi[4*k2+2],
             xr[4*k2+3], xi[4*k2+3]);
    }
}

__device__ __forceinline__ int rev4(int k) { return ((k & 3) << 2) | (k >> 2); }

__global__ void __launch_bounds__(BLOCK)
dft256_kernel(const float* __restrict__ xr, const float* __restrict__ xi,
              const float* __restrict__ Wr, const float* __restrict__ Wi,
              float* __restrict__ outR, float* __restrict__ outI)
{
    __shared__ float  shR[FPB * FSTRIDE], shI[FPB * FSTRIDE];
    __shared__ float2 tw2[NPT];          // tw2[k*16 + t] = W256^{t*k} / 16

    const int tid = threadIdx.x;
    const int f = tid >> 4;              // frame within block
    const int t = tid & 15;              // lane within frame

    // Build step-2 twiddle table from row 1 of W (W[1][c] = W256^c),
    // layout [k][t] so reads at fixed k are contiguous. Fold in 1/sqrt(256).
    {
        int k = tid >> 4, tt = tid & 15;
        int m = k * tt;                  // <= 225
        tw2[tid] = make_float2(Wr[NPT + m] * 0.0625f, Wi[NPT + m] * 0.0625f);
    }

    // ---- phase A: stage input into shared with float4 coalesced loads ----
    const size_t base = (size_t)blockIdx.x * (FPB * NPT);
    const float4* xr4 = (const float4*)(xr + base);
    const float4* xi4 = (const float4*)(xi + base);
#pragma unroll
    for (int j = 0; j < 4; j++) {
        int idx = tid + j * BLOCK;       // float4 index in block region (0..1023)
        int ff = idx >> 6;               // 64 float4 per frame
        int q  = idx & 63;
        float4 vr = __ldcs(xr4 + idx);
        float4 vi = __ldcs(xi4 + idx);
        *(float4*)&shR[ff * FSTRIDE + 4 * q] = vr;
        *(float4*)&shI[ff * FSTRIDE + 4 * q] = vi;
    }
    __syncthreads();

    // ---- phase B: strided read (conflict-free), first fft16 ----
    float* sR = shR + f * FSTRIDE;
    float* sI = shI + f * FSTRIDE;
    float ar[16], ai[16];
#pragma unroll
    for (int n2 = 0; n2 < 16; n2++) {
        ar[n2] = sR[n2 * 16 + t];
        ai[n2] = sI[n2 * 16 + t];
    }
    fft16(ar, ai);
    __syncthreads();

    // ---- phase C: twiddle by W256^{t*k}/16, write transposed ----
#pragma unroll
    for (int k = 0; k < 16; k++) {
        int s = rev4(k);
        float2 w = tw2[k * 16 + t];      // contiguous across lanes
        float vr = ar[s], vi = ai[s];
        sR[k * ROWS + t] = vr * w.x - vi * w.y;
        sI[k * ROWS + t] = vr * w.y + vi * w.x;
    }
    __syncthreads();

    // ---- phase D: row read, second fft16 ----
    float br[16], bi[16];
#pragma unroll
    for (int n1 = 0; n1 < 16; n1++) {
        br[n1] = sR[t * ROWS + n1];
        bi[n1] = sI[t * ROWS + n1];
    }
    fft16(br, bi);
    __syncthreads();

    // ---- phase E: write results back in natural frame order ----
#pragma unroll
    for (int k1 = 0; k1 < 16; k1++) {
        int s = rev4(k1);
        sR[k1 * 16 + t] = br[s];
        sI[k1 * 16 + t] = bi[s];
    }
    __syncthreads();

    // ---- phase F: float4 coalesced streaming stores ----
    float4* oR4 = (float4*)(outR + base);
    float4* oI4 = (float4*)(outI + base);
#pragma unroll
    for (int j = 0; j < 4; j++) {
        int idx = tid + j * BLOCK;
        int ff = idx >> 6;
        int q  = idx & 63;
        float4 vr = *(const float4*)&shR[ff * FSTRIDE + 4 * q];
        float4 vi = *(const float4*)&shI[ff * FSTRIDE + 4 * q];
        __stcs(oR4 + idx, vr);
        __stcs(oI4 + idx, vi);
    }
}

extern "C" void kernel_launch(void* const* d_in, const int* in_sizes, int n_in,
                              void* d_out, int out_size)
{
    const float* x_real = (const float*)d_in[0];
    const float* x_imag = (const float*)d_in[1];
    const float* W_real = (const float*)d_in[2];
    const float* W_imag = (const float*)d_in[3];

    const size_t nframes = (size_t)in_sizes[0] / NPT;   // 262144
    float* outR = (float*)d_out;
    float* outI = outR + nframes * NPT;                 // [real | imag]

    const int grid = (int)(nframes / FPB);              // 16384
    dft256_kernel<<<grid, BLOCK>>>(x_real, x_imag, W_real, W_imag, outR, outI);
}

// round 3
// speedup vs baseline: 1.1114x; 1.1114x over previous
#include <cuda_runtime.h>

// Batched 256-point complex DFT, out = FFT(x) / sqrt(256).
// Four-step: 256 = 16 x 16. 16 threads/frame, 16 frames per 256-thread block.
// Direct strided LDG.32/STG.32 (sector-coalesced); only the 16x16 transpose
// goes through shared, packed as float2 and synced with __syncwarp (frames
// never cross warps). W16 twiddles are immediates; the W256^{t*k} table
// (scale folded) is conflict-free [k][t] float2.

#define NPT      256
#define FPB      16
#define BLOCK    256
#define ROWS     17                 // padded row stride, float2 units
#define FS2      (16 * ROWS)        // frame stride, float2 units (272)

__device__ __forceinline__ void dft4(
    float& r0, float& i0, float& r1, float& i1,
    float& r2, float& i2, float& r3, float& i3)
{
    float t0r = r0 + r2, t0i = i0 + i2;
    float t1r = r0 - r2, t1i = i0 - i2;
    float t2r = r1 + r3, t2i = i1 + i3;
    float t3r = r1 - r3, t3i = i1 - i3;
    r0 = t0r + t2r;  i0 = t0i + t2i;
    r2 = t0r - t2r;  i2 = t0i - t2i;
    r1 = t1r + t3i;  i1 = t1i - t3r;   // t1 - i*t3
    r3 = t1r - t3i;  i3 = t1i + t3r;   // t1 + i*t3
}

// In-register forward 16-pt DFT (two radix-4 stages, DIT).
// Output X[4*k1+k2] lives in slot (4*k2+k1); callers remap with rev4().
__device__ __forceinline__ void fft16(float* xr, float* xi)
{
    constexpr float WR[10] = {
        1.f,  0.92387953251128674f,  0.70710678118654752f,  0.38268343236508977f,
        0.f, -0.38268343236508977f, -0.70710678118654752f, -0.92387953251128674f,
       -1.f, -0.92387953251128674f };
    constexpr float WI[10] = {
        0.f, -0.38268343236508977f, -0.70710678118654752f, -0.92387953251128674f,
       -1.f, -0.92387953251128674f, -0.70710678118654752f, -0.38268343236508977f,
        0.f,  0.38268343236508977f };

#pragma unroll
    for (int n1 = 0; n1 < 4; n1++) {
        dft4(xr[n1],    xi[n1],
             xr[n1+4],  xi[n1+4],
             xr[n1+8],  xi[n1+8],
             xr[n1+12], xi[n1+12]);
    }
#pragma unroll
    for (int n1 = 1; n1 < 4; n1++) {
#pragma unroll
        for (int k2 = 1; k2 < 4; k2++) {
            int s = n1 + 4 * k2;
            int m = n1 * k2;               // 1..9
            float wr = WR[m], wi = WI[m];
            float ar = xr[s], ai = xi[s];
            xr[s] = ar * wr - ai * wi;
            xi[s] = ar * wi + ai * wr;
        }
    }
#pragma unroll
    for (int k2 = 0; k2 < 4; k2++) {
        dft4(xr[4*k2+0], xi[4*k2+0],
             xr[4*k2+1], xi[4*k2+1],
             xr[4*k2+2], xi[4*k2+2],
             xr[4*k2+3], xi[4*k2+3]);
    }
}

__device__ __forceinline__ int rev4(int k) { return ((k & 3) << 2) | (k >> 2); }

__global__ void __launch_bounds__(BLOCK)
dft256_kernel(const float* __restrict__ xr, const float* __restrict__ xi,
              const float* __restrict__ Wr, const float* __restrict__ Wi,
              float* __restrict__ outR, float* __restrict__ outI)
{
    __shared__ float2 sh[FPB * FS2];     // transpose buffer (re,im packed)
    __shared__ float2 tw2[NPT];          // tw2[k*16+t] = W256^{t*k} / 16

    const int tid = threadIdx.x;
    const int f = tid >> 4;              // frame within block
    const int t = tid & 15;              // lane within frame (half-warp local)

    // Step-2 twiddle table from row 1 of W (W[1][c] = W256^c), scale folded.
    {
        int m = (tid >> 4) * (tid & 15); // k * t, <= 225
        tw2[tid] = make_float2(Wr[NPT + m] * 0.0625f, Wi[NPT + m] * 0.0625f);
    }
    __syncthreads();

    const size_t frame = (size_t)blockIdx.x * FPB + f;
    const float* xrp = xr + frame * NPT;
    const float* xip = xi + frame * NPT;

    // ---- step 1: strided coalesced loads, first fft16 (over n2) ----
    float ar[16], ai[16];
#pragma unroll
    for (int n2 = 0; n2 < 16; n2++) {
        ar[n2] = __ldcs(xrp + n2 * 16 + t);
        ai[n2] = __ldcs(xip + n2 * 16 + t);
    }
    fft16(ar, ai);

    // ---- step 2: twiddle W256^{t*k}/16, transposed float2 STS ----
    float2* s = sh + f * FS2;
#pragma unroll
    for (int k = 0; k < 16; k++) {
        int sl = rev4(k);
        float2 w = tw2[k * 16 + t];      // contiguous, conflict-free
        float vr = ar[sl], vi = ai[sl];
        s[k * ROWS + t] = make_float2(vr * w.x - vi * w.y,
                                      vr * w.y + vi * w.x);
    }
    __syncwarp();                        // transpose is intra-warp (2 frames/warp)

    // ---- step 3: row LDS.64, second fft16 (over n1) ----
    float br[16], bi[16];
#pragma unroll
    for (int n1 = 0; n1 < 16; n1++) {
        float2 v = s[t * ROWS + n1];
        br[n1] = v.x;  bi[n1] = v.y;
    }
    fft16(br, bi);

    // ---- step 4: strided coalesced streaming stores ----
    float* orp = outR + frame * NPT;
    float* oip = outI + frame * NPT;
#pragma unroll
    for (int k1 = 0; k1 < 16; k1++) {
        int sl = rev4(k1);
        __stcs(orp + k1 * 16 + t, br[sl]);
        __stcs(oip + k1 * 16 + t, bi[sl]);
    }
}

extern "C" void kernel_launch(void* const* d_in, const int* in_sizes, int n_in,
                              void* d_out, int out_size)
{
    const float* x_real = (const float*)d_in[0];
    const float* x_imag = (const float*)d_in[1];
    const float* W_real = (const float*)d_in[2];
    const float* W_imag = (const float*)d_in[3];

    const size_t nframes = (size_t)in_sizes[0] / NPT;   // 262144
    float* outR = (float*)d_out;
    float* outI = outR + nframes * NPT;                 // [real | imag]

    const int grid = (int)(nframes / FPB);              // 16384
    dft256_kernel<<<grid, BLOCK>>>(x_real, x_imag, W_real, W_imag, outR, outI);
}